// round 8
// baseline (speedup 1.0000x reference)
#include <cuda_runtime.h>
#include <cuda_bf16.h>
#include <math.h>
#include <stdint.h>

// Problem shapes (fixed by the dataset)
#define BSZ   8
#define LSEQ  4096
#define HDIM  512
#define PDIM  256
#define MROWS (BSZ*LSEQ)     // 32768
#define KD    512            // inner dim for both GEMMs
#define ND    512            // outer dim for both GEMMs
#define LC    64             // scan chunk length
#define NCH   (LSEQ/LC)      // 64 chunks per sequence

// GEMM tiling (mma.sync path)
#define BM 128
#define BN 128
#define BK 32
#define NK (KD/BK)           // 16 k-steps
#define STAGES 3

// smem layout (per stage), 80-byte padded rows (32 bf16 data + 8 pad)
#define ROWB 80
#define OFF_AHI 0
#define OFF_ALO (128*ROWB)              // 10240
#define OFF_WHI (2*128*ROWB)            // 20480
#define OFF_WLO (3*128*ROWB)            // 30720
#define STAGE_BYTES (4*128*ROWB)        // 40960
#define SMEM_TOTAL (STAGES*STAGE_BYTES) // 122880

// ---------------- device scratch ----------------
__device__ float2        g_Bu[(size_t)MROWS * PDIM];       // 64 MB (GEMM1 out, fp32)
__device__ __nv_bfloat16 g_Xhi[(size_t)MROWS * KD];        // 32 MB
__device__ __nv_bfloat16 g_Xlo[(size_t)MROWS * KD];        // 32 MB
__device__ __nv_bfloat16 g_A2hi[(size_t)MROWS * KD];       // 32 MB (xs split)
__device__ __nv_bfloat16 g_A2lo[(size_t)MROWS * KD];       // 32 MB
__device__ __nv_bfloat16 g_W1hi[ND * KD], g_W1lo[ND * KD];
__device__ __nv_bfloat16 g_W2hi[HDIM * KD], g_W2lo[HDIM * KD];
__device__ float2 g_lambda[PDIM];
__device__ float2 g_lampow[PDIM];
__device__ float2 g_f[PDIM];
__device__ float2 g_carry[BSZ * NCH * PDIM];
__device__ float2 g_carry_in[BSZ * NCH * PDIM];

// ---------------- PTX helpers ----------------
__device__ __forceinline__ uint32_t smem_to_u32(const void* p) {
    uint32_t a;
    asm("{ .reg .u64 t; cvta.to.shared.u64 t, %1; cvt.u32.u64 %0, t; }" : "=r"(a) : "l"(p));
    return a;
}
__device__ __forceinline__ void cp_async16(uint32_t saddr, const void* gaddr) {
    asm volatile("cp.async.cg.shared.global [%0], [%1], 16;" :: "r"(saddr), "l"(gaddr));
}
#define CP_COMMIT() asm volatile("cp.async.commit_group;" ::: "memory")
#define CP_WAIT(n)  asm volatile("cp.async.wait_group %0;" :: "n"(n) : "memory")

__device__ __forceinline__ void ldsm_x4(uint32_t* r, uint32_t addr) {
    asm volatile("ldmatrix.sync.aligned.m8n8.x4.shared.b16 {%0,%1,%2,%3}, [%4];"
        : "=r"(r[0]), "=r"(r[1]), "=r"(r[2]), "=r"(r[3]) : "r"(addr));
}
__device__ __forceinline__ void mma_bf16(float* d, const uint32_t* a, uint32_t b0, uint32_t b1) {
    asm volatile(
        "mma.sync.aligned.m16n8k16.row.col.f32.bf16.bf16.f32 "
        "{%0,%1,%2,%3}, {%4,%5,%6,%7}, {%8,%9}, {%0,%1,%2,%3};"
        : "+f"(d[0]), "+f"(d[1]), "+f"(d[2]), "+f"(d[3])
        : "r"(a[0]), "r"(a[1]), "r"(a[2]), "r"(a[3]), "r"(b0), "r"(b1));
}

// ---------------- small helpers ----------------
__device__ __forceinline__ float2 cfma(float2 l, float2 s, float2 u) {
    float2 r;
    r.x = fmaf(l.x, s.x, fmaf(-l.y, s.y, u.x));
    r.y = fmaf(l.x, s.y, fmaf( l.y, s.x, u.y));
    return r;
}
__device__ __forceinline__ void split_bf16(float v, __nv_bfloat16& hi, __nv_bfloat16& lo) {
    hi = __float2bfloat16(v);
    lo = __float2bfloat16(v - __bfloat162float(hi));
}

// ---------------- precompute kernels ----------------
__global__ void prep_params(const float* __restrict__ Lre,
                            const float* __restrict__ Lim,
                            const float* __restrict__ lstep) {
    int p = threadIdx.x;
    float step = expf(lstep[p]);
    float ar = Lre[p] * step;
    float ai = Lim[p] * step;
    double mag = exp((double)ar);
    float2 lam;
    lam.x = (float)(mag * cos((double)ai));
    lam.y = (float)(mag * sin((double)ai));
    g_lambda[p] = lam;
    double zr = lam.x, zi = lam.y;
    #pragma unroll
    for (int i = 0; i < 6; i++) {  // lam^64
        double nr = zr*zr - zi*zi, ni = 2.0*zr*zi;
        zr = nr; zi = ni;
    }
    g_lampow[p] = make_float2((float)zr, (float)zi);
    float lr = Lre[p], li = Lim[p];
    float nr = lam.x - 1.0f, ni = lam.y;
    float den = lr*lr + li*li;
    g_f[p] = make_float2((nr*lr + ni*li)/den, (ni*lr - nr*li)/den);
}

__global__ void prep_w1(const float* __restrict__ Bm) {  // B: (P,H,2)
    int idx = blockIdx.x * blockDim.x + threadIdx.x;     // over P*H
    int p = idx / HDIM, h = idx % HDIM;
    float2 f = g_f[p];
    float b0 = Bm[(size_t)(p*HDIM + h)*2 + 0];
    float b1 = Bm[(size_t)(p*HDIM + h)*2 + 1];
    float re = f.x*b0 - f.y*b1;
    float im = f.x*b1 + f.y*b0;
    __nv_bfloat16 hi, lo;
    split_bf16(re, hi, lo);
    g_W1hi[(size_t)(2*p)*KD + h] = hi;  g_W1lo[(size_t)(2*p)*KD + h] = lo;
    split_bf16(im, hi, lo);
    g_W1hi[(size_t)(2*p+1)*KD + h] = hi;  g_W1lo[(size_t)(2*p+1)*KD + h] = lo;
}

__global__ void prep_w2(const float* __restrict__ Cm) {  // C: (H,P,2)
    int idx = blockIdx.x * blockDim.x + threadIdx.x;     // over H*P
    int h = idx / PDIM, p = idx % PDIM;
    float cre =  2.0f * Cm[(size_t)(h*PDIM + p)*2 + 0];
    float cim = -2.0f * Cm[(size_t)(h*PDIM + p)*2 + 1];
    __nv_bfloat16 hi, lo;
    split_bf16(cre, hi, lo);
    g_W2hi[(size_t)h*KD + 2*p] = hi;  g_W2lo[(size_t)h*KD + 2*p] = lo;
    split_bf16(cim, hi, lo);
    g_W2hi[(size_t)h*KD + 2*p+1] = hi;  g_W2lo[(size_t)h*KD + 2*p+1] = lo;
}

__global__ void conv_x(const float* __restrict__ x) {
    size_t i = ((size_t)blockIdx.x * blockDim.x + threadIdx.x) * 4;
    float4 v = *(const float4*)(x + i);
    __nv_bfloat16 h0,l0,h1,l1,h2,l2,h3,l3;
    split_bf16(v.x, h0, l0); split_bf16(v.y, h1, l1);
    split_bf16(v.z, h2, l2); split_bf16(v.w, h3, l3);
    __nv_bfloat162 hh0; hh0.x = h0; hh0.y = h1;
    __nv_bfloat162 hh1; hh1.x = h2; hh1.y = h3;
    __nv_bfloat162 ll0; ll0.x = l0; ll0.y = l1;
    __nv_bfloat162 ll1; ll1.x = l2; ll1.y = l3;
    *(__nv_bfloat162*)(g_Xhi + i)     = hh0;
    *(__nv_bfloat162*)(g_Xhi + i + 2) = hh1;
    *(__nv_bfloat162*)(g_Xlo + i)     = ll0;
    *(__nv_bfloat162*)(g_Xlo + i + 2) = ll1;
}

// ---------------- mma.sync split-bf16 GEMM ----------------
// out[m][n] = sum_k A[m][k]*W[n][k]; A,W given as bf16 hi/lo (K-major, stride KD)
// 8 warps: wm in 0..3 (32 rows), wn in 0..1 (64 cols). Warp tile 32x64.
template<int EPI>
__global__ __launch_bounds__(256)
void gemm_mma(const __nv_bfloat16* __restrict__ Ahi, const __nv_bfloat16* __restrict__ Alo,
              const __nv_bfloat16* __restrict__ Whi, const __nv_bfloat16* __restrict__ Wlo,
              float* __restrict__ out, const float* __restrict__ Dv,
              const float* __restrict__ X) {
    extern __shared__ char smem[];
    const uint32_t sb = smem_to_u32(smem);
    const int tid  = threadIdx.x;
    const int wid  = tid >> 5;
    const int lane = tid & 31;
    const int m0 = blockIdx.y * BM;
    const int n0 = blockIdx.x * BN;
    const int wm = wid & 3;          // m warp 0..3 (32 rows each)
    const int wn = wid >> 2;         // n warp 0..1 (64 cols each)

    // cp.async loader for one stage: 4 matrices x 128 rows x 2 chunk-tasks/thread
    auto load_stage = [&](int s, int k0) {
        uint32_t st = sb + s * STAGE_BYTES;
        #pragma unroll
        for (int i = 0; i < 2; i++) {
            int task = tid + i * 256;          // 0..511
            int row = task >> 2, ch = task & 3;
            uint32_t so = (uint32_t)(row * ROWB + ch * 16);
            size_t ga = (size_t)(m0 + row) * KD + k0 + ch * 8;
            size_t gw = (size_t)(n0 + row) * KD + k0 + ch * 8;
            cp_async16(st + OFF_AHI + so, Ahi + ga);
            cp_async16(st + OFF_ALO + so, Alo + ga);
            cp_async16(st + OFF_WHI + so, Whi + gw);
            cp_async16(st + OFF_WLO + so, Wlo + gw);
        }
    };

    float acc[2][8][4];
    #pragma unroll
    for (int i = 0; i < 2; i++)
        #pragma unroll
        for (int j = 0; j < 8; j++)
            #pragma unroll
            for (int q = 0; q < 4; q++) acc[i][j][q] = 0.0f;

    load_stage(0, 0);  CP_COMMIT();
    load_stage(1, BK); CP_COMMIT();

    // ldmatrix lane addressing offsets
    const uint32_t lrow16 = (uint32_t)(lane & 15);        // row within 16
    const uint32_t lchunk = (uint32_t)((lane >> 4) << 4); // 0 or 16 bytes

    for (int k = 0; k < NK; k++) {
        CP_WAIT(1);
        __syncthreads();
        if (k + 2 < NK) { load_stage((k + 2) % STAGES, (k + 2) * BK); CP_COMMIT(); }

        const uint32_t st = sb + (k % STAGES) * STAGE_BYTES;
        const uint32_t aro0 = (uint32_t)((wm * 32 +  0) + lrow16) * ROWB;
        const uint32_t aro1 = (uint32_t)((wm * 32 + 16) + lrow16) * ROWB;

        uint32_t ahi[2][2][4], alo[2][2][4];   // [kh][mi][4]
        uint32_t bhi[2][4][4], blo[2][4][4];   // [kh][ng][4]

        // fragment loads for kh=0
        {
            const uint32_t co = lchunk;
            ldsm_x4(ahi[0][0], st + OFF_AHI + aro0 + co);
            ldsm_x4(ahi[0][1], st + OFF_AHI + aro1 + co);
            ldsm_x4(alo[0][0], st + OFF_ALO + aro0 + co);
            ldsm_x4(alo[0][1], st + OFF_ALO + aro1 + co);
            #pragma unroll
            for (int ng = 0; ng < 4; ng++) {
                uint32_t rowoff = (uint32_t)((wn * 64 + ng * 16) + lrow16) * ROWB;
                ldsm_x4(bhi[0][ng], st + OFF_WHI + rowoff + co);
                ldsm_x4(blo[0][ng], st + OFF_WLO + rowoff + co);
            }
        }
        // fragment loads for kh=1 (issued before kh=0 MMAs to overlap latency)
        {
            const uint32_t co = 32 + lchunk;
            ldsm_x4(ahi[1][0], st + OFF_AHI + aro0 + co);
            ldsm_x4(ahi[1][1], st + OFF_AHI + aro1 + co);
            ldsm_x4(alo[1][0], st + OFF_ALO + aro0 + co);
            ldsm_x4(alo[1][1], st + OFF_ALO + aro1 + co);
            #pragma unroll
            for (int ng = 0; ng < 4; ng++) {
                uint32_t rowoff = (uint32_t)((wn * 64 + ng * 16) + lrow16) * ROWB;
                ldsm_x4(bhi[1][ng], st + OFF_WHI + rowoff + co);
                ldsm_x4(blo[1][ng], st + OFF_WLO + rowoff + co);
            }
        }

        #pragma unroll
        for (int kh = 0; kh < 2; kh++) {
            #pragma unroll
            for (int mi = 0; mi < 2; mi++) {
                #pragma unroll
                for (int j = 0; j < 8; j++) {
                    const int ng = j >> 1, h = j & 1;
                    mma_bf16(acc[mi][j], ahi[kh][mi], bhi[kh][ng][h], bhi[kh][ng][h + 2]);
                    mma_bf16(acc[mi][j], ahi[kh][mi], blo[kh][ng][h], blo[kh][ng][h + 2]);
                    mma_bf16(acc[mi][j], alo[kh][mi], bhi[kh][ng][h], bhi[kh][ng][h + 2]);
                }
            }
        }
        __syncthreads();
    }

    // epilogue: d-frag mapping: d0/d1 -> (row=l>>2, col=(l&3)*2 +0/1), d2/d3 -> row+8
    #pragma unroll
    for (int mi = 0; mi < 2; mi++) {
        #pragma unroll
        for (int j = 0; j < 8; j++) {
            int r = m0 + wm * 32 + mi * 16 + (lane >> 2);
            int c = n0 + wn * 64 + j * 8 + (lane & 3) * 2;
            size_t o0 = (size_t)r * ND + c;
            size_t o1 = (size_t)(r + 8) * ND + c;
            float2 v0; v0.x = acc[mi][j][0]; v0.y = acc[mi][j][1];
            float2 v1; v1.x = acc[mi][j][2]; v1.y = acc[mi][j][3];
            if (EPI == 1) {
                float2 dv = *(const float2*)(Dv + c);
                float2 x0 = *(const float2*)(X + o0);
                float2 x1 = *(const float2*)(X + o1);
                v0.x = fmaf(dv.x, x0.x, v0.x); v0.y = fmaf(dv.y, x0.y, v0.y);
                v1.x = fmaf(dv.x, x1.x, v1.x); v1.y = fmaf(dv.y, x1.y, v1.y);
            }
            *(float2*)(out + o0) = v0;
            *(float2*)(out + o1) = v1;
        }
    }
}

// ---------------- scan kernels ----------------
__global__ void scan_carry() {
    int b = blockIdx.x / NCH;
    int c = blockIdx.x % NCH;
    int p = threadIdx.x;
    float2 lam = g_lambda[p];
    float2 s = make_float2(0.f, 0.f);
    const float2* bu = g_Bu + ((size_t)b*LSEQ + (size_t)c*LC)*PDIM + p;
    #pragma unroll 4
    for (int t = 0; t < LC; t++) {
        float2 u = bu[(size_t)t*PDIM];
        s = cfma(lam, s, u);
    }
    g_carry[((size_t)b*NCH + c)*PDIM + p] = s;
}

__global__ void scan_combine() {
    int b = blockIdx.x;
    int p = threadIdx.x;
    float2 Lp = g_lampow[p];
    float2 s = make_float2(0.f, 0.f);
    for (int c = 0; c < NCH; c++) {
        size_t idx = ((size_t)b*NCH + c)*PDIM + p;
        g_carry_in[idx] = s;
        float2 f = g_carry[idx];
        s = cfma(Lp, s, f);
    }
}

// full scan with incoming carry; write bf16 hi/lo split of xs for GEMM2
__global__ void scan_apply() {
    int b = blockIdx.x / NCH;
    int c = blockIdx.x % NCH;
    int p = threadIdx.x;
    float2 lam = g_lambda[p];
    float2 s = g_carry_in[((size_t)b*NCH + c)*PDIM + p];
    size_t row0 = (size_t)b*LSEQ + (size_t)c*LC;
    const float2* bu = g_Bu + row0*PDIM + p;
    __nv_bfloat162* outh = (__nv_bfloat162*)g_A2hi + row0*PDIM + p;
    __nv_bfloat162* outl = (__nv_bfloat162*)g_A2lo + row0*PDIM + p;
    #pragma unroll 4
    for (int t = 0; t < LC; t++) {
        float2 u = bu[(size_t)t*PDIM];
        s = cfma(lam, s, u);
        __nv_bfloat16 hr, lr, hi, li;
        split_bf16(s.x, hr, lr);
        split_bf16(s.y, hi, li);
        __nv_bfloat162 vh; vh.x = hr; vh.y = hi;
        __nv_bfloat162 vl; vl.x = lr; vl.y = li;
        outh[(size_t)t*PDIM] = vh;
        outl[(size_t)t*PDIM] = vl;
    }
}

// ---------------- launch ----------------
extern "C" void kernel_launch(void* const* d_in, const int* in_sizes, int n_in,
                              void* d_out, int out_size) {
    const float* x     = (const float*)d_in[0];
    const float* Lre   = (const float*)d_in[1];
    const float* Lim   = (const float*)d_in[2];
    const float* Bm    = (const float*)d_in[3];
    const float* Cm    = (const float*)d_in[4];
    const float* Dv    = (const float*)d_in[5];
    const float* lstep = (const float*)d_in[6];
    float* y = (float*)d_out;

    void *bu_p, *xhi_p, *xlo_p, *a2hi_p, *a2lo_p, *w1hi_p, *w1lo_p, *w2hi_p, *w2lo_p;
    cudaGetSymbolAddress(&bu_p,   g_Bu);
    cudaGetSymbolAddress(&xhi_p,  g_Xhi);
    cudaGetSymbolAddress(&xlo_p,  g_Xlo);
    cudaGetSymbolAddress(&a2hi_p, g_A2hi);
    cudaGetSymbolAddress(&a2lo_p, g_A2lo);
    cudaGetSymbolAddress(&w1hi_p, g_W1hi);
    cudaGetSymbolAddress(&w1lo_p, g_W1lo);
    cudaGetSymbolAddress(&w2hi_p, g_W2hi);
    cudaGetSymbolAddress(&w2lo_p, g_W2lo);

    cudaFuncSetAttribute(gemm_mma<0>, cudaFuncAttributeMaxDynamicSharedMemorySize, SMEM_TOTAL);
    cudaFuncSetAttribute(gemm_mma<1>, cudaFuncAttributeMaxDynamicSharedMemorySize, SMEM_TOTAL);

    prep_params<<<1, PDIM>>>(Lre, Lim, lstep);
    prep_w1<<<(PDIM*HDIM)/256, 256>>>(Bm);
    prep_w2<<<(HDIM*PDIM)/256, 256>>>(Cm);
    conv_x<<<(size_t)MROWS*KD/4/256, 256>>>(x);

    dim3 gg(ND/BN, MROWS/BM);  // (4, 256)
    gemm_mma<0><<<gg, 256, SMEM_TOTAL>>>((const __nv_bfloat16*)xhi_p, (const __nv_bfloat16*)xlo_p,
                                         (const __nv_bfloat16*)w1hi_p, (const __nv_bfloat16*)w1lo_p,
                                         (float*)bu_p, nullptr, nullptr);

    scan_carry  <<<BSZ*NCH, PDIM>>>();
    scan_combine<<<BSZ,     PDIM>>>();
    scan_apply  <<<BSZ*NCH, PDIM>>>();

    gemm_mma<1><<<gg, 256, SMEM_TOTAL>>>((const __nv_bfloat16*)a2hi_p, (const __nv_bfloat16*)a2lo_p,
                                         (const __nv_bfloat16*)w2hi_p, (const __nv_bfloat16*)w2lo_p,
                                         y, Dv, x);
}